// round 12
// baseline (speedup 1.0000x reference)
#include <cuda_runtime.h>
#include <cuda_bf16.h>
#include <cstdint>

#define NPATH 15
#define NUNIT 51

__constant__ int c_l1[NPATH] = {0,0,0,1,1,1,1,1,1,2,2,2,2,2,2};
__constant__ int c_l2[NPATH] = {0,1,2,0,1,1,1,2,2,0,1,1,2,2,2};
__constant__ int c_lo[NPATH] = {0,1,2,1,0,1,2,1,2,2,1,2,0,1,2};

// 9 passes, one ko each; units = (path, k-within-lo)
__constant__ int U_path[NUNIT] = {
    0,4,12,
    1,3,5,7,10,13,  1,3,5,7,10,13,  1,3,5,7,10,13,
    2,6,8,9,11,14,  2,6,8,9,11,14,  2,6,8,9,11,14,  2,6,8,9,11,14,  2,6,8,9,11,14};
__constant__ int U_k[NUNIT] = {
    0,0,0,
    0,0,0,0,0,0,  1,1,1,1,1,1,  2,2,2,2,2,2,
    0,0,0,0,0,0,  1,1,1,1,1,1,  2,2,2,2,2,2,  3,3,3,3,3,3,  4,4,4,4,4,4};
__constant__ int U_end[9] = {3,9,15,21,27,33,39,45,51};

__device__ float g_w3j[NPATH * 125];
__device__ uint4 g_Whfrag[NPATH * 2048];   // [p][kk][ntpIdx][lane] mma-frag order (hi)
__device__ uint4 g_Wlfrag[NPATH * 2048];   // (lo)

// smem layout (dynamic), 64-sample tile, double-buffered A + sC, no W staging
#define SO_X2  0
#define SO_SC0 2304
#define SO_SC1 3584
#define SO_A0  8192
#define SO_A1  40960
#define SMEM_BYTES 73728

#define THREADS 256
#define TILE_Z 64

// ---------------- merged setup ----------------
__device__ __forceinline__ void qentry(int l, int r, int c, float& re, float& im) {
    int m = r - l;
    const float s2 = 0.70710678118654752440f;
    float a = 0.0f, b = 0.0f;
    if (m < 0) {
        if (c == l - m)      a = s2;
        else if (c == l + m) b = -s2;
    } else if (m == 0) {
        if (c == l) a = 1.0f;
    } else {
        float sg = (m & 1) ? -1.0f : 1.0f;
        if (c == l + m)      a = sg * s2;
        else if (c == l - m) b = sg * s2;
    }
    switch (l & 3) {
        case 0: re = a;  im = b;  break;
        case 1: re = b;  im = -a; break;
        case 2: re = -a; im = -b; break;
        default: re = -b; im = a; break;
    }
}

__device__ float su2_cg(int j1, int m1, int j2, int m2, int j3, int m3) {
    if (m3 != m1 + m2) return 0.0f;
    const float F[8] = {1.0f, 1.0f, 2.0f, 6.0f, 24.0f, 120.0f, 720.0f, 5040.0f};
    int vmin = -j1 + j2 + m3; if (-j1 + m1 > vmin) vmin = -j1 + m1; if (vmin < 0) vmin = 0;
    int vmax = j2 + j3 + m1; if (j3 - j1 + j2 < vmax) vmax = j3 - j1 + j2; if (j3 + m3 < vmax) vmax = j3 + m3;
    float C = sqrtf((2.0f * j3 + 1.0f)
                    * F[j3 + j1 - j2] * F[j3 - j1 + j2] * F[j1 + j2 - j3] / F[j1 + j2 + j3 + 1]
                    * F[j3 + m3] * F[j3 - m3]
                    / (F[j1 - m1] * F[j1 + m1] * F[j2 - m2] * F[j2 + m2]));
    float S = 0.0f;
    for (int v = vmin; v <= vmax; v++) {
        float sgn = ((v + j2 + m2) & 1) ? -1.0f : 1.0f;
        S += sgn / F[v] * F[j2 + j3 + m1 - v] * F[j1 - m1 + v]
             / (F[j3 - j1 + j2 - v] * F[j3 + m3 - v] * F[v + j1 - j2 - m3]);
    }
    return C * S;
}

__global__ void setup_kernel(const float* __restrict__ wt) {
    __shared__ float red[128];
    int blk = blockIdx.x;
    int tid = threadIdx.x;

    if (blk < 120) {
        // ---- W fragment tables (hi + lo), kk = seg ----
        int p = blk >> 3;
        int kk = blk & 7;
        int ntpIdx = tid >> 5;      // 0..7
        int lane = tid & 31;
        uint32_t regsH[4], regsL[4];
#pragma unroll
        for (int r = 0; r < 4; r++) {
            int rr = r & 1, ns = r >> 1;
            int k = kk * 16 + rr * 8 + (lane & 3) * 2;
            int nn = (ntpIdx * 2 + ns) * 8 + (lane >> 2);
            float v0 = wt[p * 16384 + k * 128 + nn];
            float h0 = __bfloat162float(__float2bfloat16(v0));
            float v1 = wt[p * 16384 + (k + 1) * 128 + nn];
            float h1 = __bfloat162float(__float2bfloat16(v1));
            uint32_t pkH, pkL;
            asm("cvt.rn.bf16x2.f32 %0, %1, %2;" : "=r"(pkH) : "f"(h1), "f"(h0));
            asm("cvt.rn.bf16x2.f32 %0, %1, %2;" : "=r"(pkL) : "f"(v1 - h1), "f"(v0 - h0));
            regsH[r] = pkH;
            regsL[r] = pkL;
        }
        uint4 qh; qh.x = regsH[0]; qh.y = regsH[1]; qh.z = regsH[2]; qh.w = regsH[3];
        uint4 ql; ql.x = regsL[0]; ql.y = regsL[1]; ql.z = regsL[2]; ql.w = regsL[3];
        int off = ((p * 8 + kk) * 8 + ntpIdx) * 32 + lane;
        g_Whfrag[off] = qh;
        g_Wlfrag[off] = ql;
        return;
    }

    // ---- w3j (fp32, validated) ----
    int p = blk - 120;
    int l1 = c_l1[p], l2 = c_l2[p], l3 = c_lo[p];
    int n1 = 2 * l1 + 1, n2 = 2 * l2 + 1, n3 = 2 * l3 + 1;
    int a = tid / 25, b = (tid / 5) % 5, cc = tid % 5;

    float val = 0.0f;
    if (tid < 125 && a < n1 && b < n2 && cc < n3) {
        for (int i = 0; i < n1; i++) {
            float q1r, q1i; qentry(l1, i, a, q1r, q1i);
            if (q1r == 0.0f && q1i == 0.0f) continue;
            for (int k = 0; k < n2; k++) {
                float q2r, q2i; qentry(l2, k, b, q2r, q2i);
                if (q2r == 0.0f && q2i == 0.0f) continue;
                float pr = q1r * q2r - q1i * q2i;
                float pi = q1r * q2i + q1i * q2r;
                for (int nn = 0; nn < n3; nn++) {
                    float q3r, q3i; qentry(l3, nn, cc, q3r, q3i);
                    if (q3r == 0.0f && q3i == 0.0f) continue;
                    float cg = su2_cg(l1, i - l1, l2, k - l2, l3, nn - l3);
                    if (cg == 0.0f) continue;
                    val += cg * (pr * q3r + pi * q3i);
                }
            }
        }
    }

    if (tid < 128) red[tid] = val * val;
    __syncthreads();
    for (int s = 64; s > 0; s >>= 1) {
        if (tid < s && tid + s < 128) red[tid] += red[tid + s];
        __syncthreads();
    }
    float norm = sqrtf(red[0]);
    const int iocnt[3] = {3, 6, 6};
    float alpha = sqrtf((float)(2 * l3 + 1) / (128.0f * (float)iocnt[l3]));
    float outv = 0.0f;
    if (norm > 0.0f) outv = val / norm * alpha;
    if (tid < 125) g_w3j[p * 125 + tid] = outv;
}

// ---------------- mma helpers ----------------
__device__ __forceinline__ uint32_t smem_u32(const void* p) {
    uint32_t a;
    asm("{ .reg .u64 t; cvta.to.shared.u64 t, %1; cvt.u32.u64 %0, t; }" : "=r"(a) : "l"(p));
    return a;
}
__device__ __forceinline__ void ldsm_x4(uint32_t* r, uint32_t a) {
    asm volatile("ldmatrix.sync.aligned.m8n8.x4.shared.b16 {%0,%1,%2,%3}, [%4];"
                 : "=r"(r[0]), "=r"(r[1]), "=r"(r[2]), "=r"(r[3]) : "r"(a));
}
__device__ __forceinline__ void mma16816(float (&d)[4], const uint32_t* a, const uint32_t* b) {
    asm volatile("mma.sync.aligned.m16n8k16.row.col.f32.bf16.bf16.f32 "
                 "{%0,%1,%2,%3}, {%4,%5,%6,%7}, {%8,%9}, {%0,%1,%2,%3};"
                 : "+f"(d[0]), "+f"(d[1]), "+f"(d[2]), "+f"(d[3])
                 : "r"(a[0]), "r"(a[1]), "r"(a[2]), "r"(a[3]), "r"(b[0]), "r"(b[1]));
}

// Warp tile: 16 z-rows x 64 w-cols. A rows 64, row stride 256B, lo at +16KB.
// B (hi and lo) fetched from global fragment tables.
__device__ __forceinline__ void mma_phase(uint32_t Ab,
                                          const uint4* __restrict__ whf,
                                          const uint4* __restrict__ wlf,
                                          float (&acc)[8][4], int lane,
                                          int zrow0, int nh) {
    const int m = lane >> 3, r = lane & 7;
#pragma unroll
    for (int kk = 0; kk < 8; kk++) {
        uint32_t ah[4], al[4];
        const int gc = kk * 2 + (m >> 1);
        const int row = zrow0 + r + (m & 1) * 8;
        uint32_t aaddr = Ab + (uint32_t)(row * 256 + ((gc ^ (row & 7)) << 4));
        ldsm_x4(ah, aaddr);
        ldsm_x4(al, aaddr + 16384u);
#pragma unroll
        for (int ntp = 0; ntp < 4; ntp++) {
            int fo = (kk * 8 + nh * 4 + ntp) * 32 + lane;
            uint4 bhv = __ldg(whf + fo);
            uint4 blv = __ldg(wlf + fo);
            uint32_t bh[4] = {bhv.x, bhv.y, bhv.z, bhv.w};
            uint32_t bl[4] = {blv.x, blv.y, blv.z, blv.w};
#pragma unroll
            for (int q = 0; q < 2; q++) {
                mma16816(acc[ntp * 2 + q], ah, bh + q * 2);
                mma16816(acc[ntp * 2 + q], ah, bl + q * 2);
                mma16816(acc[ntp * 2 + q], al, bh + q * 2);
            }
        }
    }
}

__device__ __forceinline__ void store_acc(float (&acc)[8][4], float* __restrict__ out,
                                          int ko, int z0, int zrow0, int nh,
                                          int lane, int n) {
    const int col0 = nh * 64 + (lane & 3) * 2;
    const int r0 = z0 + zrow0 + (lane >> 2);
#pragma unroll
    for (int nt = 0; nt < 8; nt++) {
        if (r0 < n)
            *(float2*)(out + (long)r0 * 1152 + ko * 128 + col0 + nt * 8) =
                make_float2(acc[nt][0], acc[nt][1]);
        if (r0 + 8 < n)
            *(float2*)(out + (long)(r0 + 8) * 1152 + ko * 128 + col0 + nt * 8) =
                make_float2(acc[nt][2], acc[nt][3]);
        acc[nt][0] = acc[nt][1] = acc[nt][2] = acc[nt][3] = 0.0f;
    }
}

// ---------------- sC compute for one unit ----------------
__device__ __forceinline__ void compute_sC(float* sC, const float* sX2, int p, int k) {
    const int t = threadIdx.x;
    if (t < TILE_Z) {
        const int l1 = c_l1[p], l2 = c_l2[p];
        const int n1 = 2 * l1 + 1, n2 = 2 * l2 + 1;
        const int s2 = l2 * l2;
        for (int i = 0; i < n1; i++) {
            float s = 0.0f;
            for (int j = 0; j < n2; j++)
                s += g_w3j[p * 125 + (i * 5 + j) * 5 + k] * sX2[t * 9 + s2 + j];
            sC[t * 5 + i] = s;
        }
    }
}

// ---------------- templated A-tile build (64 z x 128 u, single k) ----------------
template<int N1>
__device__ __forceinline__ void build_A(char* Abuf, const float* __restrict__ x1,
                                        const float* __restrict__ sC, long z0,
                                        int s1, int n, bool full) {
    const int t = threadIdx.x;
#pragma unroll 4
    for (int it = 0; it < 16; it++) {
        int idx = t + it * THREADS;
        int z = idx >> 6, u2 = idx & 63;
        long zg = z0 + z;
        float2 xv[N1];
        const float* xr = x1 + zg * 1152 + s1 * 128 + u2 * 2;
        if (full || zg < n) {
#pragma unroll
            for (int i = 0; i < N1; i++) xv[i] = *(const float2*)(xr + i * 128);
        } else {
#pragma unroll
            for (int i = 0; i < N1; i++) { xv[i].x = 0.0f; xv[i].y = 0.0f; }
        }
        uint32_t boff = (uint32_t)(z * 256 + (((u2 >> 2) ^ (z & 7)) << 4) + (u2 & 3) * 4);
        float a0 = 0.0f, a1 = 0.0f;
#pragma unroll
        for (int i = 0; i < N1; i++) {
            float c = sC[z * 5 + i];
            a0 = fmaf(c, xv[i].x, a0);
            a1 = fmaf(c, xv[i].y, a1);
        }
        uint32_t hp;
        asm("cvt.rn.bf16x2.f32 %0, %1, %2;" : "=r"(hp) : "f"(a1), "f"(a0));
        float h0 = __uint_as_float(hp << 16);
        float h1 = __uint_as_float(hp & 0xffff0000u);
        uint32_t lp;
        asm("cvt.rn.bf16x2.f32 %0, %1, %2;" : "=r"(lp) : "f"(a1 - h1), "f"(a0 - h0));
        *(uint32_t*)(Abuf + boff) = hp;
        *(uint32_t*)(Abuf + 16384 + boff) = lp;
    }
}

__device__ __forceinline__ void build_dispatch(char* Abuf, const float* __restrict__ x1,
                                               const float* sC, long z0, int p,
                                               int n, bool full) {
    const int l1 = c_l1[p];
    const int s1 = l1 * l1;
    if (l1 == 0)      build_A<1>(Abuf, x1, sC, z0, s1, n, full);
    else if (l1 == 1) build_A<3>(Abuf, x1, sC, z0, s1, n, full);
    else              build_A<5>(Abuf, x1, sC, z0, s1, n, full);
}

// ---------------- main kernel: software-pipelined units ----------------
__global__ __launch_bounds__(THREADS, 3)
void tp_mma_kernel(const float* __restrict__ x1, const float* __restrict__ x2,
                   float* __restrict__ out, int n) {
    extern __shared__ __align__(1024) char smem[];
    uint32_t sb = smem_u32(smem);
    const int t = threadIdx.x;
    const int wid = t >> 5, lane = t & 31;
    const int z0 = blockIdx.x * TILE_Z;
    const int zrow0 = (wid >> 1) * 16;     // 4 z-tiles of 16
    const int nh = wid & 1;                // warp n-half
    const bool full = (z0 + TILE_Z <= n);

    float* sX2 = (float*)(smem + SO_X2);
    float* sC0 = (float*)(smem + SO_SC0);
    float* sC1 = (float*)(smem + SO_SC1);
    char*  A0  = smem + SO_A0;
    char*  A1  = smem + SO_A1;

    for (int idx = t; idx < TILE_Z * 9; idx += THREADS) {
        int z = idx / 9, j = idx - z * 9;
        int zg = z0 + z;
        sX2[idx] = (full || zg < n) ? x2[(long)zg * 9 + j] : 0.0f;
    }

    float acc[8][4];
#pragma unroll
    for (int nt = 0; nt < 8; nt++)
#pragma unroll
        for (int j = 0; j < 4; j++) acc[nt][j] = 0.0f;

    // ---- prologue: sC(0); build A(0); sC(1) ----
    __syncthreads();
    compute_sC(sC0, sX2, U_path[0], U_k[0]);
    __syncthreads();
    build_dispatch(A0, x1, sC0, z0, U_path[0], n, full);
    compute_sC(sC1, sX2, U_path[1], U_k[1]);
    __syncthreads();

    int pass = 0;

    for (int e = 0; e < NUNIT; e++) {
        const int p = U_path[e];
        char* Acur = (e & 1) ? A1 : A0;

        // MMA(e) first: feeds the tensor pipe while other warps still build
        mma_phase(smem_u32(Acur), g_Whfrag + p * 2048, g_Wlfrag + p * 2048,
                  acc, lane, zrow0, nh);

        if (e == U_end[pass] - 1) {
            store_acc(acc, out, pass, z0, zrow0, nh, lane, n);
            pass++;
        }

        // build A(e+1) into the other buffer
        if (e + 1 < NUNIT) {
            char* Anext = ((e + 1) & 1) ? A1 : A0;
            float* sCnext = ((e + 1) & 1) ? sC1 : sC0;
            build_dispatch(Anext, x1, sCnext, z0, U_path[e + 1], n, full);
        }
        // sC(e+2) into the buffer freed this phase
        if (e + 2 < NUNIT) {
            float* sCnn = (e & 1) ? sC1 : sC0;
            compute_sC(sCnn, sX2, U_path[e + 2], U_k[e + 2]);
        }
        __syncthreads();
    }
}

// ---------------------------------------------------------------------------

extern "C" void kernel_launch(void* const* d_in, const int* in_sizes, int n_in,
                              void* d_out, int out_size) {
    const float* x1 = (const float*)d_in[0];   // (N, 9, 128)
    const float* x2 = (const float*)d_in[1];   // (N, 9, 1)
    const float* wt = (const float*)d_in[2];   // (15*128*128,)
    float* out = (float*)d_out;                // (N, 9, 128)

    int n = in_sizes[0] / 1152;

    setup_kernel<<<135, 256>>>(wt);

    cudaFuncSetAttribute(tp_mma_kernel, cudaFuncAttributeMaxDynamicSharedMemorySize, SMEM_BYTES);
    tp_mma_kernel<<<(n + TILE_Z - 1) / TILE_Z, THREADS, SMEM_BYTES>>>(x1, x2, out, n);
}

// round 13
// speedup vs baseline: 1.6830x; 1.6830x over previous
#include <cuda_runtime.h>
#include <cuda_fp16.h>
#include <cstdint>

#define NPATH 15
#define NENT 33

__constant__ int c_l1[NPATH] = {0,0,0,1,1,1,1,1,1,2,2,2,2,2,2};
__constant__ int c_l2[NPATH] = {0,1,2,0,1,1,1,2,2,0,1,1,2,2,2};
__constant__ int c_lo[NPATH] = {0,1,2,1,0,1,2,1,2,2,1,2,0,1,2};

// schedule: 5 passes over ko slots {0,1},{2,3},{4,5},{6,7},{8}
__constant__ int S_path[NENT] = {0,4,12,1,3,5,7,10,13, 1,3,5,7,10,13, 2,6,8,9,11,14, 2,6,8,9,11,14, 2,6,8,9,11,14};
__constant__ int S_k0[NENT]   = {0,0,0, 0,0,0,0,0,0,   1,1,1,1,1,1,   0,0,0,0,0,0,   2,2,2,2,2,2,   4,4,4,4,4,4};
__constant__ int S_nk[NENT]   = {1,1,1, 1,1,1,1,1,1,   2,2,2,2,2,2,   2,2,2,2,2,2,   2,2,2,2,2,2,   1,1,1,1,1,1};
__constant__ int S_slot[NENT] = {0,0,0, 1,1,1,1,1,1,   0,0,0,0,0,0,   0,0,0,0,0,0,   0,0,0,0,0,0,   0,0,0,0,0,0};
__constant__ int P_end[5] = {9,15,21,27,33};
__constant__ int P_kob[5] = {0,2,4,6,8};
__constant__ int P_ns[5]  = {2,2,2,2,1};

__device__ float g_w3j[NPATH * 125];
__device__ __half g_Wh[NPATH * 16384];   // fp16, swizzled [u-row 256B]

// smem layout (dynamic), 64-sample tile (round-10 layout, Wl table removed)
#define SO_X2 0
#define SO_SC 2304
#define SO_WH 8192
#define SO_A0 40960
#define SO_A1 73728
#define SMEM_BYTES 106496

#define THREADS 256
#define TILE_Z 64

// ---------------- merged setup ----------------
__device__ __forceinline__ void qentry(int l, int r, int c, float& re, float& im) {
    int m = r - l;
    const float s2 = 0.70710678118654752440f;
    float a = 0.0f, b = 0.0f;
    if (m < 0) {
        if (c == l - m)      a = s2;
        else if (c == l + m) b = -s2;
    } else if (m == 0) {
        if (c == l) a = 1.0f;
    } else {
        float sg = (m & 1) ? -1.0f : 1.0f;
        if (c == l + m)      a = sg * s2;
        else if (c == l - m) b = sg * s2;
    }
    switch (l & 3) {
        case 0: re = a;  im = b;  break;
        case 1: re = b;  im = -a; break;
        case 2: re = -a; im = -b; break;
        default: re = -b; im = a; break;
    }
}

__device__ float su2_cg(int j1, int m1, int j2, int m2, int j3, int m3) {
    if (m3 != m1 + m2) return 0.0f;
    const float F[8] = {1.0f, 1.0f, 2.0f, 6.0f, 24.0f, 120.0f, 720.0f, 5040.0f};
    int vmin = -j1 + j2 + m3; if (-j1 + m1 > vmin) vmin = -j1 + m1; if (vmin < 0) vmin = 0;
    int vmax = j2 + j3 + m1; if (j3 - j1 + j2 < vmax) vmax = j3 - j1 + j2; if (j3 + m3 < vmax) vmax = j3 + m3;
    float C = sqrtf((2.0f * j3 + 1.0f)
                    * F[j3 + j1 - j2] * F[j3 - j1 + j2] * F[j1 + j2 - j3] / F[j1 + j2 + j3 + 1]
                    * F[j3 + m3] * F[j3 - m3]
                    / (F[j1 - m1] * F[j1 + m1] * F[j2 - m2] * F[j2 + m2]));
    float S = 0.0f;
    for (int v = vmin; v <= vmax; v++) {
        float sgn = ((v + j2 + m2) & 1) ? -1.0f : 1.0f;
        S += sgn / F[v] * F[j2 + j3 + m1 - v] * F[j1 - m1 + v]
             / (F[j3 - j1 + j2 - v] * F[j3 + m3 - v] * F[v + j1 - j2 - m3]);
    }
    return C * S;
}

__global__ void setup_kernel(const float* __restrict__ wt) {
    __shared__ float red[128];
    int blk = blockIdx.x;
    int tid = threadIdx.x;

    if (blk < 120) {
        int p = blk >> 3;
        int seg = blk & 7;
        // ---- Wh: fp16 + swizzle (row u = 256B, granule XOR) ----
        int base = seg * 2048;
        for (int q = tid; q < 2048; q += 256) {
            int idx = base + q;
            int u = idx >> 7, w = idx & 127;
            float v = wt[p * 16384 + idx];
            uint32_t off = (uint32_t)(u * 256 + (((w >> 3) ^ (u & 7)) << 4) + (w & 7) * 2);
            *(__half*)((char*)g_Wh + p * 32768 + off) = __float2half_rn(v);
        }
        return;
    }

    // ---- w3j (fp32, validated) ----
    int p = blk - 120;
    int l1 = c_l1[p], l2 = c_l2[p], l3 = c_lo[p];
    int n1 = 2 * l1 + 1, n2 = 2 * l2 + 1, n3 = 2 * l3 + 1;
    int a = tid / 25, b = (tid / 5) % 5, cc = tid % 5;

    float val = 0.0f;
    if (tid < 125 && a < n1 && b < n2 && cc < n3) {
        for (int i = 0; i < n1; i++) {
            float q1r, q1i; qentry(l1, i, a, q1r, q1i);
            if (q1r == 0.0f && q1i == 0.0f) continue;
            for (int k = 0; k < n2; k++) {
                float q2r, q2i; qentry(l2, k, b, q2r, q2i);
                if (q2r == 0.0f && q2i == 0.0f) continue;
                float pr = q1r * q2r - q1i * q2i;
                float pi = q1r * q2i + q1i * q2r;
                for (int nn = 0; nn < n3; nn++) {
                    float q3r, q3i; qentry(l3, nn, cc, q3r, q3i);
                    if (q3r == 0.0f && q3i == 0.0f) continue;
                    float cg = su2_cg(l1, i - l1, l2, k - l2, l3, nn - l3);
                    if (cg == 0.0f) continue;
                    val += cg * (pr * q3r + pi * q3i);
                }
            }
        }
    }

    if (tid < 128) red[tid] = val * val;
    __syncthreads();
    for (int s = 64; s > 0; s >>= 1) {
        if (tid < s && tid + s < 128) red[tid] += red[tid + s];
        __syncthreads();
    }
    float norm = sqrtf(red[0]);
    const int iocnt[3] = {3, 6, 6};
    float alpha = sqrtf((float)(2 * l3 + 1) / (128.0f * (float)iocnt[l3]));
    float outv = 0.0f;
    if (norm > 0.0f) outv = val / norm * alpha;
    if (tid < 125) g_w3j[p * 125 + tid] = outv;
}

// ---------------- mma helpers ----------------
__device__ __forceinline__ uint32_t smem_u32(const void* p) {
    uint32_t a;
    asm("{ .reg .u64 t; cvta.to.shared.u64 t, %1; cvt.u32.u64 %0, t; }" : "=r"(a) : "l"(p));
    return a;
}
__device__ __forceinline__ void cp_async16(uint32_t dst, const void* src) {
    asm volatile("cp.async.cg.shared.global [%0], [%1], 16;" :: "r"(dst), "l"(src));
}
__device__ __forceinline__ void ldsm_x4(uint32_t* r, uint32_t a) {
    asm volatile("ldmatrix.sync.aligned.m8n8.x4.shared.b16 {%0,%1,%2,%3}, [%4];"
                 : "=r"(r[0]), "=r"(r[1]), "=r"(r[2]), "=r"(r[3]) : "r"(a));
}
__device__ __forceinline__ void ldsm_x4t(uint32_t* r, uint32_t a) {
    asm volatile("ldmatrix.sync.aligned.m8n8.x4.trans.shared.b16 {%0,%1,%2,%3}, [%4];"
                 : "=r"(r[0]), "=r"(r[1]), "=r"(r[2]), "=r"(r[3]) : "r"(a));
}
__device__ __forceinline__ void mma16816(float (&d)[4], const uint32_t* a, const uint32_t* b) {
    asm volatile("mma.sync.aligned.m16n8k16.row.col.f32.f16.f16.f32 "
                 "{%0,%1,%2,%3}, {%4,%5,%6,%7}, {%8,%9}, {%0,%1,%2,%3};"
                 : "+f"(d[0]), "+f"(d[1]), "+f"(d[2]), "+f"(d[3])
                 : "r"(a[0]), "r"(a[1]), "r"(a[2]), "r"(a[3]), "r"(b[0]), "r"(b[1]));
}

// Warp tile: 16 z-rows x 64 w-cols. A rows 64, row stride 256B, lo at +16KB.
// 2-product scheme: D = Ah*Wh + Al*Wh (exact A, fp16-truncated W).
__device__ __forceinline__ void mma_phase(uint32_t Ab, uint32_t Wb,
                                          float (&acc)[8][4], int lane,
                                          int zrow0, int nh) {
    const int m = lane >> 3, r = lane & 7;
#pragma unroll
    for (int kk = 0; kk < 8; kk++) {
        uint32_t ah[4], al[4];
        const int gc = kk * 2 + (m >> 1);
        const int row = zrow0 + r + (m & 1) * 8;
        uint32_t aaddr = Ab + (uint32_t)(row * 256 + ((gc ^ (row & 7)) << 4));
        ldsm_x4(ah, aaddr);
        ldsm_x4(al, aaddr + 16384u);
        const int krow = kk * 16 + ((m & 1) << 3) + r;
        const int swr = krow & 7;
        const uint32_t brow_base = Wb + (uint32_t)(krow * 256);
#pragma unroll
        for (int ntp = 0; ntp < 4; ntp++) {
            int ntg = nh * 8 + ntp * 2 + (m >> 1);
            uint32_t baddr = brow_base + (uint32_t)((ntg ^ swr) << 4);
            uint32_t bh[4];
            ldsm_x4t(bh, baddr);
#pragma unroll
            for (int q = 0; q < 2; q++) {
                mma16816(acc[ntp * 2 + q], ah, bh + q * 2);
                mma16816(acc[ntp * 2 + q], al, bh + q * 2);
            }
        }
    }
}

__device__ __forceinline__ void store_acc(float (&acc)[8][4], float* __restrict__ out,
                                          int ko, int z0, int zrow0, int nh,
                                          int lane, int n) {
    const int col0 = nh * 64 + (lane & 3) * 2;
    const int r0 = z0 + zrow0 + (lane >> 2);
#pragma unroll
    for (int nt = 0; nt < 8; nt++) {
        if (r0 < n)
            *(float2*)(out + (long)r0 * 1152 + ko * 128 + col0 + nt * 8) =
                make_float2(acc[nt][0], acc[nt][1]);
        if (r0 + 8 < n)
            *(float2*)(out + (long)(r0 + 8) * 1152 + ko * 128 + col0 + nt * 8) =
                make_float2(acc[nt][2], acc[nt][3]);
        acc[nt][0] = acc[nt][1] = acc[nt][2] = acc[nt][3] = 0.0f;
    }
}

// ---------------- templated A-tile build (64 z x 128 u, fp16 hi/lo exact split) ----------------
template<int N1, int NK>
__device__ __forceinline__ void build_A(char* smem, const float* __restrict__ x1,
                                        const float* __restrict__ sC, long z0,
                                        int s1, int n, bool full) {
    const int t = threadIdx.x;
#pragma unroll 4
    for (int it = 0; it < 16; it++) {
        int idx = t + it * THREADS;
        int z = idx >> 6, u2 = idx & 63;
        long zg = z0 + z;
        float2 xv[N1];
        const float* xr = x1 + zg * 1152 + s1 * 128 + u2 * 2;
        if (full || zg < n) {
#pragma unroll
            for (int i = 0; i < N1; i++) xv[i] = *(const float2*)(xr + i * 128);
        } else {
#pragma unroll
            for (int i = 0; i < N1; i++) { xv[i].x = 0.0f; xv[i].y = 0.0f; }
        }
        uint32_t boff = (uint32_t)(z * 256 + (((u2 >> 2) ^ (z & 7)) << 4) + (u2 & 3) * 4);
#pragma unroll
        for (int kq = 0; kq < NK; kq++) {
            float a0 = 0.0f, a1 = 0.0f;
#pragma unroll
            for (int i = 0; i < N1; i++) {
                float c = sC[z * 12 + i * 2 + kq];
                a0 = fmaf(c, xv[i].x, a0);
                a1 = fmaf(c, xv[i].y, a1);
            }
            __half h0 = __float2half_rn(a0);
            __half h1 = __float2half_rn(a1);
            uint32_t hp = ((uint32_t)__half_as_ushort(h1) << 16) | __half_as_ushort(h0);
            __half l0 = __float2half_rn(a0 - __half2float(h0));
            __half l1 = __float2half_rn(a1 - __half2float(h1));
            uint32_t lp = ((uint32_t)__half_as_ushort(l1) << 16) | __half_as_ushort(l0);
            char* base = smem + (kq ? SO_A1 : SO_A0) + boff;
            *(uint32_t*)base = hp;
            *(uint32_t*)(base + 16384) = lp;
        }
    }
}

// ---------------- main kernel ----------------
__global__ __launch_bounds__(THREADS, 2)
void tp_mma_kernel(const float* __restrict__ x1, const float* __restrict__ x2,
                   float* __restrict__ out, int n) {
    extern __shared__ __align__(1024) char smem[];
    uint32_t sb = smem_u32(smem);
    const int t = threadIdx.x;
    const int wid = t >> 5, lane = t & 31;
    const int z0 = blockIdx.x * TILE_Z;
    const int zrow0 = (wid >> 1) * 16;     // 4 z-tiles of 16
    const int nh = wid & 1;                // warp n-half
    const bool full = (z0 + TILE_Z <= n);

    float* sX2 = (float*)(smem + SO_X2);
    float* sC  = (float*)(smem + SO_SC);

    for (int idx = t; idx < TILE_Z * 9; idx += THREADS) {
        int z = idx / 9, j = idx - z * 9;
        int zg = z0 + z;
        sX2[idx] = (full || zg < n) ? x2[(long)zg * 9 + j] : 0.0f;
    }

    float acc0[8][4], acc1[8][4];
#pragma unroll
    for (int nt = 0; nt < 8; nt++)
#pragma unroll
        for (int j = 0; j < 4; j++) { acc0[nt][j] = 0.0f; acc1[nt][j] = 0.0f; }

    int pass = 0;

    for (int e = 0; e < NENT; e++) {
        const int p = S_path[e], k0 = S_k0[e], nk = S_nk[e], sl = S_slot[e];
        const int l1 = c_l1[p], l2 = c_l2[p];
        const int n1 = 2 * l1 + 1, n2 = 2 * l2 + 1;
        const int s1 = l1 * l1, s2 = l2 * l2;

        __syncthreads();   // prior MMA reads done before overwriting W/A/sC

        // stage Wh via cp.async (overlaps with c + A build below)
        {
            const char* srcH = (const char*)g_Wh + p * 32768;
#pragma unroll
            for (int i = 0; i < 8; i++) {
                int q = (t + i * THREADS) * 16;
                cp_async16(sb + SO_WH + q, srcH + q);
            }
            asm volatile("cp.async.commit_group;" ::: "memory");
        }

        // c[z][i][kq]
        if (t < TILE_Z) {
            for (int i = 0; i < n1; i++)
                for (int kq = 0; kq < nk; kq++) {
                    int k = k0 + kq;
                    float s = 0.0f;
                    for (int j = 0; j < n2; j++)
                        s += g_w3j[p * 125 + (i * 5 + j) * 5 + k] * sX2[t * 9 + s2 + j];
                    sC[t * 12 + i * 2 + kq] = s;
                }
        }
        __syncthreads();

        // build A tiles (fp16 hi/lo exact split, swizzled)
        if (nk == 1) {
            if (n1 == 1)      build_A<1,1>(smem, x1, sC, z0, s1, n, full);
            else if (n1 == 3) build_A<3,1>(smem, x1, sC, z0, s1, n, full);
            else              build_A<5,1>(smem, x1, sC, z0, s1, n, full);
        } else {
            if (n1 == 1)      build_A<1,2>(smem, x1, sC, z0, s1, n, full);
            else if (n1 == 3) build_A<3,2>(smem, x1, sC, z0, s1, n, full);
            else              build_A<5,2>(smem, x1, sC, z0, s1, n, full);
        }
        asm volatile("cp.async.wait_group 0;" ::: "memory");
        __syncthreads();

        // MMA (2 products: exact-A fp16 pair x truncated-W fp16)
        uint32_t Wb = sb + SO_WH;
        if (nk == 1) {
            if (sl == 0) mma_phase(sb + SO_A0, Wb, acc0, lane, zrow0, nh);
            else         mma_phase(sb + SO_A0, Wb, acc1, lane, zrow0, nh);
        } else {
            mma_phase(sb + SO_A0, Wb, acc0, lane, zrow0, nh);
            mma_phase(sb + SO_A1, Wb, acc1, lane, zrow0, nh);
        }

        // pass epilogue
        if (e == P_end[pass] - 1) {
            int kob = P_kob[pass], ns = P_ns[pass];
            store_acc(acc0, out, kob, z0, zrow0, nh, lane, n);
            if (ns == 2) store_acc(acc1, out, kob + 1, z0, zrow0, nh, lane, n);
            pass++;
        }
    }
}

// ---------------------------------------------------------------------------

extern "C" void kernel_launch(void* const* d_in, const int* in_sizes, int n_in,
                              void* d_out, int out_size) {
    const float* x1 = (const float*)d_in[0];   // (N, 9, 128)
    const float* x2 = (const float*)d_in[1];   // (N, 9, 1)
    const float* wt = (const float*)d_in[2];   // (15*128*128,)
    float* out = (float*)d_out;                // (N, 9, 128)

    int n = in_sizes[0] / 1152;

    setup_kernel<<<135, 256>>>(wt);

    cudaFuncSetAttribute(tp_mma_kernel, cudaFuncAttributeMaxDynamicSharedMemorySize, SMEM_BYTES);
    tp_mma_kernel<<<(n + TILE_Z - 1) / TILE_Z, THREADS, SMEM_BYTES>>>(x1, x2, out, n);
}